// round 8
// baseline (speedup 1.0000x reference)
#include <cuda_runtime.h>
#include <cstdint>

#define Hh 256
#define Tt 187
#define Bb 1024
#define Cc 5
#define CLW 4                   // cluster width (CTAs per cluster)
#define MB 32                   // batch rows per cluster
#define THR 256
#define NCTA ((Bb / MB) * CLW)  // 128 CTAs = 32 clusters x 4

union F2U { unsigned long long u; float2 f; };

__device__ __forceinline__ unsigned long long f32x2_fma(
    unsigned long long a, unsigned long long b, unsigned long long c) {
    unsigned long long d;
    asm("fma.rn.f32x2 %0, %1, %2, %3;" : "=l"(d) : "l"(a), "l"(b), "l"(c));
    return d;
}

__device__ __forceinline__ uint32_t smem_u32(const void* p) {
    uint32_t a;
    asm("{ .reg .u64 t; cvta.to.shared.u64 t, %1; cvt.u32.u64 %0, t; }"
        : "=r"(a) : "l"(p));
    return a;
}

// Store 4B to the same smem offset in CTA `peer` of this cluster.
__device__ __forceinline__ void dsmem_store(uint32_t laddr, uint32_t peer, float v) {
    asm volatile(
        "{\n\t.reg .b32 ra;\n\t"
        "mapa.shared::cluster.u32 ra, %0, %1;\n\t"
        "st.shared::cluster.f32 [ra], %2;\n\t}"
        :: "r"(laddr), "r"(peer), "f"(v) : "memory");
}

__device__ __forceinline__ void cluster_arrive_() {
    asm volatile("barrier.cluster.arrive.aligned;" ::: "memory");
}
__device__ __forceinline__ void cluster_wait_() {
    asm volatile("barrier.cluster.wait.aligned;" ::: "memory");
}

struct Smem {
    float h0[2][MB * Hh];       // 64 KB double-buffered layer-0 hidden
    float h1[2][MB * Hh];       // 64 KB double-buffered layer-1 hidden
    float part[CLW][MB][64];    // 32 KB k-split partials [kg][row][col]
    float xs[MB][Tt + 1];       // ~24 KB staged x
};

__global__ void __launch_bounds__(THR, 1) __cluster_dims__(CLW, 1, 1)
rnn_cluster_kernel(
    const float* __restrict__ x,
    const float* __restrict__ W_ih0, const float* __restrict__ W_hh0,
    const float* __restrict__ b_ih0, const float* __restrict__ b_hh0,
    const float* __restrict__ W_ih1, const float* __restrict__ W_hh1,
    const float* __restrict__ b_ih1, const float* __restrict__ b_hh1,
    const float* __restrict__ W_fc,  const float* __restrict__ b_fc,
    float* __restrict__ out)
{
    extern __shared__ __align__(16) char raw[];
    Smem& S = *reinterpret_cast<Smem*>(raw);

    const int t   = threadIdx.x;
    const int col = t & 63;          // column within this CTA's 64-col slice
    const int kg  = t >> 6;          // k-group 0..3 (64 k each)
    uint32_t rank;
    asm("mov.u32 %0, %%cluster_ctarank;" : "=r"(rank));
    const int colg = (int)rank * 64 + col;   // global output column
    const int k0   = kg * 64;                // this thread's k-slice start
    const int b0   = (blockIdx.x / CLW) * MB;

    // ---- resident weights: 192 floats = 96 f32x2 register pairs ------------
    unsigned long long w0u[32], wau[32], wbu[32];
    #pragma unroll
    for (int i = 0; i < 16; ++i) {
        ulonglong2 v0 = *reinterpret_cast<const ulonglong2*>(
            &W_hh0[colg * Hh + k0 + i * 4]);
        w0u[2*i] = v0.x; w0u[2*i+1] = v0.y;
        ulonglong2 va = *reinterpret_cast<const ulonglong2*>(
            &W_ih1[colg * Hh + k0 + i * 4]);
        wau[2*i] = va.x; wau[2*i+1] = va.y;
        ulonglong2 vb = *reinterpret_cast<const ulonglong2*>(
            &W_hh1[colg * Hh + k0 + i * 4]);
        wbu[2*i] = vb.x; wbu[2*i+1] = vb.y;
    }
    const float wih0  = W_ih0[colg];
    const float bias0 = b_ih0[colg] + b_hh0[colg];
    const float bias1 = b_ih1[colg] + b_hh1[colg];

    // ---- stage x, zero hidden buffers --------------------------------------
    for (int i = t; i < MB * Tt; i += THR) {
        int r = i / Tt, c = i % Tt;
        S.xs[r][c] = x[(b0 + r) * Tt + c];
    }
    for (int i = t; i < MB * Hh; i += THR) {
        S.h0[0][i] = 0.f; S.h0[1][i] = 0.f;
        S.h1[0][i] = 0.f; S.h1[1][i] = 0.f;
    }
    cluster_arrive_(); cluster_wait_();

    const int myrow0 = kg * 8;       // reducer role: 8 rows for this thread
    int cur = 0;

    for (int step = 0; step < Tt; ++step) {
        const int nxt = cur ^ 1;

        // ===== layer 0 partials over this thread's 64-k slice ===============
        for (int rg = 0; rg < MB; rg += 2) {
            unsigned long long a0 = 0ULL, a1 = 0ULL;
            const float* h0a = &S.h0[cur][rg * Hh + k0];
            const float* h0b = &S.h0[cur][(rg + 1) * Hh + k0];
            #pragma unroll
            for (int kk = 0; kk < 16; ++kk) {
                ulonglong2 ha = *reinterpret_cast<const ulonglong2*>(h0a + kk * 4);
                ulonglong2 hb = *reinterpret_cast<const ulonglong2*>(h0b + kk * 4);
                a0 = f32x2_fma(ha.x, w0u[2*kk],   a0);
                a0 = f32x2_fma(ha.y, w0u[2*kk+1], a0);
                a1 = f32x2_fma(hb.x, w0u[2*kk],   a1);
                a1 = f32x2_fma(hb.y, w0u[2*kk+1], a1);
            }
            F2U u0; u0.u = a0; S.part[kg][rg][col]     = u0.f.x + u0.f.y;
            F2U u1; u1.u = a1; S.part[kg][rg + 1][col] = u1.f.x + u1.f.y;
        }
        __syncthreads();

        // ===== layer 0 reduce + tanh, write h0' to all 4 CTAs ===============
        {
            float hv[8];
            #pragma unroll
            for (int i = 0; i < 8; ++i) {
                int r = myrow0 + i;
                float s = (S.part[0][r][col] + S.part[1][r][col])
                        + (S.part[2][r][col] + S.part[3][r][col]);
                hv[i] = tanhf(S.xs[r][step] * wih0 + bias0 + s);
            }
            #pragma unroll
            for (int i = 0; i < 8; ++i) {
                uint32_t la = smem_u32(&S.h0[nxt][(myrow0 + i) * Hh + colg]);
                #pragma unroll
                for (uint32_t p = 0; p < CLW; ++p) dsmem_store(la, p, hv[i]);
            }
        }
        cluster_arrive_(); cluster_wait_();

        // ===== layer 1 partials =============================================
        for (int rg = 0; rg < MB; rg += 2) {
            unsigned long long a0 = 0ULL, a1 = 0ULL;
            const float* pa0 = &S.h0[nxt][rg * Hh + k0];
            const float* pa1 = &S.h0[nxt][(rg + 1) * Hh + k0];
            const float* pb0 = &S.h1[cur][rg * Hh + k0];
            const float* pb1 = &S.h1[cur][(rg + 1) * Hh + k0];
            #pragma unroll
            for (int kk = 0; kk < 16; ++kk) {
                ulonglong2 ha = *reinterpret_cast<const ulonglong2*>(pa0 + kk * 4);
                ulonglong2 hb = *reinterpret_cast<const ulonglong2*>(pa1 + kk * 4);
                ulonglong2 ga = *reinterpret_cast<const ulonglong2*>(pb0 + kk * 4);
                ulonglong2 gb = *reinterpret_cast<const ulonglong2*>(pb1 + kk * 4);
                a0 = f32x2_fma(ha.x, wau[2*kk],   a0);
                a0 = f32x2_fma(ha.y, wau[2*kk+1], a0);
                a0 = f32x2_fma(ga.x, wbu[2*kk],   a0);
                a0 = f32x2_fma(ga.y, wbu[2*kk+1], a0);
                a1 = f32x2_fma(hb.x, wau[2*kk],   a1);
                a1 = f32x2_fma(hb.y, wau[2*kk+1], a1);
                a1 = f32x2_fma(gb.x, wbu[2*kk],   a1);
                a1 = f32x2_fma(gb.y, wbu[2*kk+1], a1);
            }
            F2U u0; u0.u = a0; S.part[kg][rg][col]     = u0.f.x + u0.f.y;
            F2U u1; u1.u = a1; S.part[kg][rg + 1][col] = u1.f.x + u1.f.y;
        }
        __syncthreads();

        // ===== layer 1 reduce + tanh, write h1' to all 4 CTAs ===============
        {
            float hv[8];
            #pragma unroll
            for (int i = 0; i < 8; ++i) {
                int r = myrow0 + i;
                float s = (S.part[0][r][col] + S.part[1][r][col])
                        + (S.part[2][r][col] + S.part[3][r][col]);
                hv[i] = tanhf(bias1 + s);
            }
            #pragma unroll
            for (int i = 0; i < 8; ++i) {
                uint32_t la = smem_u32(&S.h1[nxt][(myrow0 + i) * Hh + colg]);
                #pragma unroll
                for (uint32_t p = 0; p < CLW; ++p) dsmem_store(la, p, hv[i]);
            }
        }
        cluster_arrive_(); cluster_wait_();

        cur = nxt;
    }

    // ---- final FC: each CTA writes its 8 rows (h1 fully replicated) --------
    if (t < Cc * 8) {
        int c = t >> 3;
        int r = (int)rank * 8 + (t & 7);
        float s = b_fc[c];
        #pragma unroll 8
        for (int h = 0; h < Hh; ++h)
            s += S.h1[cur][r * Hh + h] * W_fc[c * Hh + h];
        out[(b0 + r) * Cc + c] = s;
    }
}

extern "C" void kernel_launch(void* const* d_in, const int* in_sizes, int n_in,
                              void* d_out, int out_size) {
    const float* x     = (const float*)d_in[0];
    const float* W_ih0 = (const float*)d_in[1];
    const float* W_hh0 = (const float*)d_in[2];
    const float* b_ih0 = (const float*)d_in[3];
    const float* b_hh0 = (const float*)d_in[4];
    const float* W_ih1 = (const float*)d_in[5];
    const float* W_hh1 = (const float*)d_in[6];
    const float* b_ih1 = (const float*)d_in[7];
    const float* b_hh1 = (const float*)d_in[8];
    const float* W_fc  = (const float*)d_in[9];
    const float* b_fc  = (const float*)d_in[10];
    float* out = (float*)d_out;

    static int configured = 0;
    if (!configured) {
        cudaFuncSetAttribute(rnn_cluster_kernel,
                             cudaFuncAttributeMaxDynamicSharedMemorySize,
                             (int)sizeof(Smem));
        configured = 1;
    }
    rnn_cluster_kernel<<<NCTA, THR, sizeof(Smem)>>>(
        x, W_ih0, W_hh0, b_ih0, b_hh0,
        W_ih1, W_hh1, b_ih1, b_hh1, W_fc, b_fc, out);
}

// round 11
// speedup vs baseline: 1.9645x; 1.9645x over previous
#include <cuda_runtime.h>
#include <cstdint>

#define Hh 256
#define Tt 187
#define Bb 1024
#define Cc 5
#define MBc 16                    // batch rows per cluster
#define THR 256
#define NCTA ((Bb / MBc) * 2)     // 128 CTAs = 64 clusters x 2

// Packed weights: [k/4][j][4] so lane j loads float4 of 4 consecutive k's,
// coalesced across lanes (16B/lane, lanes = consecutive j).
__device__ float g_Wp0[Hh * Hh];
__device__ float g_Wpih1[Hh * Hh];
__device__ float g_Wp1[Hh * Hh];

__global__ void pack_kernel(const float* __restrict__ W_hh0,
                            const float* __restrict__ W_ih1,
                            const float* __restrict__ W_hh1) {
    int j = blockIdx.x, k = threadIdx.x;
    int src = j * Hh + k;
    int dst = ((k >> 2) * Hh + j) * 4 + (k & 3);
    g_Wp0[dst]   = W_hh0[src];
    g_Wpih1[dst] = W_ih1[src];
    g_Wp1[dst]   = W_hh1[src];
}

union F2U { unsigned long long u; float2 f; };

__device__ __forceinline__ unsigned long long f32x2_fma(
    unsigned long long a, unsigned long long b, unsigned long long c) {
    unsigned long long d;
    asm("fma.rn.f32x2 %0, %1, %2, %3;" : "=l"(d) : "l"(a), "l"(b), "l"(c));
    return d;
}

__device__ __forceinline__ uint32_t smem_u32(const void* p) {
    uint32_t a;
    asm("{ .reg .u64 t; cvta.to.shared.u64 t, %1; cvt.u32.u64 %0, t; }"
        : "=r"(a) : "l"(p));
    return a;
}

// 16B store to the same smem offset in peer CTA of this cluster.
__device__ __forceinline__ void dsmem_st128(uint32_t laddr, uint32_t peer,
                                            float4 v) {
    asm volatile(
        "{\n\t.reg .b32 ra;\n\t"
        "mapa.shared::cluster.u32 ra, %0, %1;\n\t"
        "st.shared::cluster.v4.f32 [ra], {%2, %3, %4, %5};\n\t}"
        :: "r"(laddr), "r"(peer), "f"(v.x), "f"(v.y), "f"(v.z), "f"(v.w)
        : "memory");
}

__device__ __forceinline__ void cluster_sync_() {
    asm volatile("barrier.cluster.arrive.aligned;" ::: "memory");
    asm volatile("barrier.cluster.wait.aligned;" ::: "memory");
}

struct Smem {
    float h0[2][MBc][Hh];        // 32 KB double-buffered
    float h1[2][MBc][Hh];        // 32 KB
    float part[4][MBc][128];     // 32 KB  [kg][row][local col]
    float xs[MBc][Tt + 1];       // ~12 KB
    float wih0s[Hh], bias0s[Hh], bias1s[Hh];
};

__global__ void __launch_bounds__(THR, 1) __cluster_dims__(2, 1, 1)
rnn_cluster2_kernel(
    const float* __restrict__ x,
    const float* __restrict__ W_ih0,
    const float* __restrict__ b_ih0, const float* __restrict__ b_hh0,
    const float* __restrict__ b_ih1, const float* __restrict__ b_hh1,
    const float* __restrict__ W_fc,  const float* __restrict__ b_fc,
    float* __restrict__ out)
{
    extern __shared__ __align__(16) char raw[];
    Smem& S = *reinterpret_cast<Smem*>(raw);

    const int t    = threadIdx.x;
    const int lane = t & 31;
    const int w    = t >> 5;
    const int kg   = w >> 1;            // k-group 0..3  (k-slice of 64)
    const int rh   = w & 1;             // row half: rows [8*rh, 8*rh+8)
    uint32_t rank;
    asm("mov.u32 %0, %%cluster_ctarank;" : "=r"(rank));
    const int colbase = (int)rank * 128;   // this CTA's 128 output columns
    const int b0      = (blockIdx.x >> 1) * MBc;

    // ---- stage x, biases; zero hidden ----------------------------------
    for (int i = t; i < MBc * Tt; i += THR) {
        int r = i / Tt, c = i % Tt;
        S.xs[r][c] = x[(b0 + r) * Tt + c];
    }
    for (int i = t; i < Hh; i += THR) {
        S.wih0s[i]  = W_ih0[i];
        S.bias0s[i] = b_ih0[i] + b_hh0[i];
        S.bias1s[i] = b_ih1[i] + b_hh1[i];
    }
    for (int i = t; i < 2 * MBc * Hh; i += THR) {
        (&S.h0[0][0][0])[i] = 0.f;
        (&S.h1[0][0][0])[i] = 0.f;
    }
    cluster_sync_();

    const int k4lo = kg * 16;
    const int row0 = rh * 8;
    // reducer role: rows {2*rp, 2*rp+1}, local cols [4*cq, 4*cq+4)
    const int rp = t >> 5;              // 0..7
    const int cq = lane;                // 0..31
    const uint32_t peer = rank ^ 1u;

    int cur = 0;
    for (int step = 0; step < Tt; ++step) {
        const int nxt = cur ^ 1;

        // ===== layer 0 partials: 8 rows x 4 cols over k-slice 64 =========
        {
            unsigned long long acc[8][4];
            #pragma unroll
            for (int r = 0; r < 8; ++r)
                #pragma unroll
                for (int c = 0; c < 4; ++c) acc[r][c] = 0ULL;

            #pragma unroll 4
            for (int kk = 0; kk < 16; ++kk) {
                const int k4 = k4lo + kk;
                ulonglong2 wv[4];
                #pragma unroll
                for (int c = 0; c < 4; ++c)
                    wv[c] = *reinterpret_cast<const ulonglong2*>(
                        &g_Wp0[(k4 * Hh + colbase + lane + 32 * c) * 4]);
                #pragma unroll
                for (int r = 0; r < 8; ++r) {
                    ulonglong2 h = *reinterpret_cast<const ulonglong2*>(
                        &S.h0[cur][row0 + r][k4 * 4]);
                    #pragma unroll
                    for (int c = 0; c < 4; ++c) {
                        acc[r][c] = f32x2_fma(h.x, wv[c].x, acc[r][c]);
                        acc[r][c] = f32x2_fma(h.y, wv[c].y, acc[r][c]);
                    }
                }
            }
            #pragma unroll
            for (int r = 0; r < 8; ++r)
                #pragma unroll
                for (int c = 0; c < 4; ++c) {
                    F2U u; u.u = acc[r][c];
                    S.part[kg][row0 + r][lane + 32 * c] = u.f.x + u.f.y;
                }
        }
        __syncthreads();

        // ===== layer 0 reduce + tanh; write h0' local + peer =============
        #pragma unroll
        for (int rr = 0; rr < 2; ++rr) {
            const int r = 2 * rp + rr;
            float4 v;
            float* vp = &v.x;
            #pragma unroll
            for (int i = 0; i < 4; ++i) {
                int c = 4 * cq + i;
                float s = (S.part[0][r][c] + S.part[1][r][c])
                        + (S.part[2][r][c] + S.part[3][r][c]);
                int gj = colbase + c;
                vp[i] = tanhf(S.xs[r][step] * S.wih0s[gj] + S.bias0s[gj] + s);
            }
            *reinterpret_cast<float4*>(&S.h0[nxt][r][colbase + 4 * cq]) = v;
            dsmem_st128(smem_u32(&S.h0[nxt][r][colbase + 4 * cq]), peer, v);
        }
        cluster_sync_();

        // ===== layer 1 partials ==========================================
        {
            unsigned long long acc[8][4];
            #pragma unroll
            for (int r = 0; r < 8; ++r)
                #pragma unroll
                for (int c = 0; c < 4; ++c) acc[r][c] = 0ULL;

            #pragma unroll 2
            for (int kk = 0; kk < 16; ++kk) {
                const int k4 = k4lo + kk;
                ulonglong2 wa[4], wb[4];
                #pragma unroll
                for (int c = 0; c < 4; ++c) {
                    wa[c] = *reinterpret_cast<const ulonglong2*>(
                        &g_Wpih1[(k4 * Hh + colbase + lane + 32 * c) * 4]);
                    wb[c] = *reinterpret_cast<const ulonglong2*>(
                        &g_Wp1[(k4 * Hh + colbase + lane + 32 * c) * 4]);
                }
                #pragma unroll
                for (int r = 0; r < 8; ++r) {
                    ulonglong2 ha = *reinterpret_cast<const ulonglong2*>(
                        &S.h0[nxt][row0 + r][k4 * 4]);
                    ulonglong2 hb = *reinterpret_cast<const ulonglong2*>(
                        &S.h1[cur][row0 + r][k4 * 4]);
                    #pragma unroll
                    for (int c = 0; c < 4; ++c) {
                        acc[r][c] = f32x2_fma(ha.x, wa[c].x, acc[r][c]);
                        acc[r][c] = f32x2_fma(ha.y, wa[c].y, acc[r][c]);
                        acc[r][c] = f32x2_fma(hb.x, wb[c].x, acc[r][c]);
                        acc[r][c] = f32x2_fma(hb.y, wb[c].y, acc[r][c]);
                    }
                }
            }
            #pragma unroll
            for (int r = 0; r < 8; ++r)
                #pragma unroll
                for (int c = 0; c < 4; ++c) {
                    F2U u; u.u = acc[r][c];
                    S.part[kg][row0 + r][lane + 32 * c] = u.f.x + u.f.y;
                }
        }
        __syncthreads();

        // ===== layer 1 reduce + tanh; write h1' local + peer =============
        #pragma unroll
        for (int rr = 0; rr < 2; ++rr) {
            const int r = 2 * rp + rr;
            float4 v;
            float* vp = &v.x;
            #pragma unroll
            for (int i = 0; i < 4; ++i) {
                int c = 4 * cq + i;
                float s = (S.part[0][r][c] + S.part[1][r][c])
                        + (S.part[2][r][c] + S.part[3][r][c]);
                vp[i] = tanhf(S.bias1s[colbase + c] + s);
            }
            *reinterpret_cast<float4*>(&S.h1[nxt][r][colbase + 4 * cq]) = v;
            dsmem_st128(smem_u32(&S.h1[nxt][r][colbase + 4 * cq]), peer, v);
        }
        cluster_sync_();

        cur = nxt;
    }

    // ---- final FC: rank 0 writes the cluster's 16 rows ------------------
    if (rank == 0 && t < Cc * MBc) {
        int c = t / MBc, r = t % MBc;
        float s = b_fc[c];
        #pragma unroll 8
        for (int h = 0; h < Hh; ++h)
            s += S.h1[cur][r][h] * W_fc[c * Hh + h];
        out[(b0 + r) * Cc + c] = s;
    }
    cluster_sync_();   // peer must not exit while rank0 still reads own smem
}

extern "C" void kernel_launch(void* const* d_in, const int* in_sizes, int n_in,
                              void* d_out, int out_size) {
    const float* x     = (const float*)d_in[0];
    const float* W_ih0 = (const float*)d_in[1];
    const float* W_hh0 = (const float*)d_in[2];
    const float* b_ih0 = (const float*)d_in[3];
    const float* b_hh0 = (const float*)d_in[4];
    const float* W_ih1 = (const float*)d_in[5];
    const float* W_hh1 = (const float*)d_in[6];
    const float* b_ih1 = (const float*)d_in[7];
    const float* b_hh1 = (const float*)d_in[8];
    const float* W_fc  = (const float*)d_in[9];
    const float* b_fc  = (const float*)d_in[10];
    float* out = (float*)d_out;

    cudaFuncSetAttribute(rnn_cluster2_kernel,
                         cudaFuncAttributeMaxDynamicSharedMemorySize,
                         (int)sizeof(Smem));
    pack_kernel<<<Hh, Hh>>>(W_hh0, W_ih1, W_hh1);
    rnn_cluster2_kernel<<<NCTA, THR, sizeof(Smem)>>>(
        x, W_ih0, b_ih0, b_hh0, b_ih1, b_hh1, W_fc, b_fc, out);
}

// round 12
// speedup vs baseline: 2.0353x; 1.0361x over previous
#include <cuda_runtime.h>

#define Hh 256
#define Tt 187
#define Bb 1024
#define Cc 5
#define MB 8
#define NCTA (Bb / MB)   // 128 CTAs, 1 per SM
#define THR 512          // 16 warps = 128 jj-lanes x 4 k-groups

// Packed weights: [k/4][j][4] so lane j loads float4 of 4 consecutive k's,
// coalesced across lanes (16B/lane, lanes = consecutive j).
__device__ float g_Wp0[Hh * Hh];
__device__ float g_Wpih1[Hh * Hh];
__device__ float g_Wp1[Hh * Hh];

__global__ void pack_kernel(const float* __restrict__ W_hh0,
                            const float* __restrict__ W_ih1,
                            const float* __restrict__ W_hh1) {
    int j = blockIdx.x, k = threadIdx.x;
    int src = j * Hh + k;
    int dst = ((k >> 2) * Hh + j) * 4 + (k & 3);
    g_Wp0[dst]   = W_hh0[src];
    g_Wpih1[dst] = W_ih1[src];
    g_Wp1[dst]   = W_hh1[src];
}

union F2U { unsigned long long u; float2 f; };

__device__ __forceinline__ unsigned long long f32x2_fma(
    unsigned long long a, unsigned long long b, unsigned long long c) {
    unsigned long long d;
    asm("fma.rn.f32x2 %0, %1, %2, %3;" : "=l"(d) : "l"(a), "l"(b), "l"(c));
    return d;
}

struct Smem {
    float h0[MB][Hh];            // 8 KB  (in-place; phase barriers order RAW)
    float h1[MB][Hh];            // 8 KB
    float part[4][MB][Hh];       // 32 KB [kg][row][col]
    float xs[MB][Tt + 1];        // ~6 KB
    float wih0s[Hh], bias0s[Hh], bias1s[Hh];
};

__global__ void __launch_bounds__(THR, 1) rnn_fused_kernel(
    const float* __restrict__ x,
    const float* __restrict__ W_ih0,
    const float* __restrict__ b_ih0, const float* __restrict__ b_hh0,
    const float* __restrict__ b_ih1, const float* __restrict__ b_hh1,
    const float* __restrict__ W_fc,  const float* __restrict__ b_fc,
    float* __restrict__ out)
{
    extern __shared__ __align__(16) char raw[];
    Smem& S = *reinterpret_cast<Smem*>(raw);

    const int t  = threadIdx.x;
    const int jj = t & 127;          // first owned column; second is jj+128
    const int kg = t >> 7;           // k-group 0..3 (64 k = 16 k4 each)
    const int b0 = blockIdx.x * MB;

    for (int i = t; i < MB * Tt; i += THR) {
        int r = i / Tt, c = i % Tt;
        S.xs[r][c] = x[(b0 + r) * Tt + c];
    }
    for (int i = t; i < Hh; i += THR) {
        S.wih0s[i]  = W_ih0[i];
        S.bias0s[i] = b_ih0[i] + b_hh0[i];
        S.bias1s[i] = b_ih1[i] + b_hh1[i];
    }
    for (int i = t; i < MB * Hh; i += THR) {
        (&S.h0[0][0])[i] = 0.f;
        (&S.h1[0][0])[i] = 0.f;
    }
    __syncthreads();

    const int k4lo = kg * 16;

    for (int step = 0; step < Tt; ++step) {
        // ===== layer 0 partials: 2 cols x 8 rows over k-slice of 64 ======
        {
            unsigned long long a0[MB], a1[MB];
            #pragma unroll
            for (int b = 0; b < MB; ++b) { a0[b] = 0ULL; a1[b] = 0ULL; }

            #pragma unroll 4
            for (int kk = 0; kk < 16; ++kk) {
                const int k4 = k4lo + kk;
                ulonglong2 w0 = *reinterpret_cast<const ulonglong2*>(
                    &g_Wp0[(k4 * Hh + jj) * 4]);
                ulonglong2 w1 = *reinterpret_cast<const ulonglong2*>(
                    &g_Wp0[(k4 * Hh + jj + 128) * 4]);
                #pragma unroll
                for (int b = 0; b < MB; ++b) {
                    ulonglong2 h = *reinterpret_cast<const ulonglong2*>(
                        &S.h0[b][k4 * 4]);
                    a0[b] = f32x2_fma(h.x, w0.x, a0[b]);
                    a0[b] = f32x2_fma(h.y, w0.y, a0[b]);
                    a1[b] = f32x2_fma(h.x, w1.x, a1[b]);
                    a1[b] = f32x2_fma(h.y, w1.y, a1[b]);
                }
            }
            #pragma unroll
            for (int b = 0; b < MB; ++b) {
                F2U u0; u0.u = a0[b];
                S.part[kg][b][jj] = u0.f.x + u0.f.y;
                F2U u1; u1.u = a1[b];
                S.part[kg][b][jj + 128] = u1.f.x + u1.f.y;
            }
        }
        __syncthreads();   // all reads of h0 done; parts visible

        // ===== layer 0 reduce + tanh (512 threads x 4 items = 2048) ======
        #pragma unroll
        for (int i = 0; i < 4; ++i) {
            int idx = t + THR * i;
            int col = idx & 255, b = idx >> 8;
            float s = (S.part[0][b][col] + S.part[1][b][col])
                    + (S.part[2][b][col] + S.part[3][b][col]);
            float pre = S.xs[b][step] * S.wih0s[col] + S.bias0s[col] + s;
            S.h0[b][col] = tanhf(pre);
        }
        __syncthreads();   // new h0 visible

        // ===== layer 1 partials ==========================================
        {
            unsigned long long a0[MB], a1[MB];
            #pragma unroll
            for (int b = 0; b < MB; ++b) { a0[b] = 0ULL; a1[b] = 0ULL; }

            #pragma unroll 4
            for (int kk = 0; kk < 16; ++kk) {
                const int k4 = k4lo + kk;
                ulonglong2 wa0 = *reinterpret_cast<const ulonglong2*>(
                    &g_Wpih1[(k4 * Hh + jj) * 4]);
                ulonglong2 wa1 = *reinterpret_cast<const ulonglong2*>(
                    &g_Wpih1[(k4 * Hh + jj + 128) * 4]);
                ulonglong2 wb0 = *reinterpret_cast<const ulonglong2*>(
                    &g_Wp1[(k4 * Hh + jj) * 4]);
                ulonglong2 wb1 = *reinterpret_cast<const ulonglong2*>(
                    &g_Wp1[(k4 * Hh + jj + 128) * 4]);
                #pragma unroll
                for (int b = 0; b < MB; ++b) {
                    ulonglong2 ha = *reinterpret_cast<const ulonglong2*>(
                        &S.h0[b][k4 * 4]);
                    ulonglong2 hb = *reinterpret_cast<const ulonglong2*>(
                        &S.h1[b][k4 * 4]);
                    a0[b] = f32x2_fma(ha.x, wa0.x, a0[b]);
                    a0[b] = f32x2_fma(ha.y, wa0.y, a0[b]);
                    a0[b] = f32x2_fma(hb.x, wb0.x, a0[b]);
                    a0[b] = f32x2_fma(hb.y, wb0.y, a0[b]);
                    a1[b] = f32x2_fma(ha.x, wa1.x, a1[b]);
                    a1[b] = f32x2_fma(ha.y, wa1.y, a1[b]);
                    a1[b] = f32x2_fma(hb.x, wb1.x, a1[b]);
                    a1[b] = f32x2_fma(hb.y, wb1.y, a1[b]);
                }
            }
            #pragma unroll
            for (int b = 0; b < MB; ++b) {
                F2U u0; u0.u = a0[b];
                S.part[kg][b][jj] = u0.f.x + u0.f.y;
                F2U u1; u1.u = a1[b];
                S.part[kg][b][jj + 128] = u1.f.x + u1.f.y;
            }
        }
        __syncthreads();

        // ===== layer 1 reduce + tanh =====================================
        #pragma unroll
        for (int i = 0; i < 4; ++i) {
            int idx = t + THR * i;
            int col = idx & 255, b = idx >> 8;
            float s = (S.part[0][b][col] + S.part[1][b][col])
                    + (S.part[2][b][col] + S.part[3][b][col]);
            S.h1[b][col] = tanhf(S.bias1s[col] + s);
        }
        __syncthreads();
    }

    // ---- final FC: out[b] = h1_last @ W_fc^T + b_fc ---------------------
    if (t < Cc * MB) {
        int c = t / MB, b = t % MB;
        float s = b_fc[c];
        #pragma unroll 8
        for (int h = 0; h < Hh; ++h)
            s += S.h1[b][h] * W_fc[c * Hh + h];
        out[(b0 + b) * Cc + c] = s;
    }
}

extern "C" void kernel_launch(void* const* d_in, const int* in_sizes, int n_in,
                              void* d_out, int out_size) {
    const float* x     = (const float*)d_in[0];
    const float* W_ih0 = (const float*)d_in[1];
    const float* W_hh0 = (const float*)d_in[2];
    const float* b_ih0 = (const float*)d_in[3];
    const float* b_hh0 = (const float*)d_in[4];
    const float* W_ih1 = (const float*)d_in[5];
    const float* W_hh1 = (const float*)d_in[6];
    const float* b_ih1 = (const float*)d_in[7];
    const float* b_hh1 = (const float*)d_in[8];
    const float* W_fc  = (const float*)d_in[9];
    const float* b_fc  = (const float*)d_in[10];
    float* out = (float*)d_out;

    cudaFuncSetAttribute(rnn_fused_kernel,
                         cudaFuncAttributeMaxDynamicSharedMemorySize,
                         (int)sizeof(Smem));
    pack_kernel<<<Hh, Hh>>>(W_hh0, W_ih1, W_hh1);
    rnn_fused_kernel<<<NCTA, THR, sizeof(Smem)>>>(
        x, W_ih0, b_ih0, b_hh0, b_ih1, b_hh1, W_fc, b_fc, out);
}